// round 2
// baseline (speedup 1.0000x reference)
#include <cuda_runtime.h>
#include <cuda_bf16.h>
#include <cstdint>

// Problem constants
#define B_   4
#define C_   8192
#define HW_  1024
#define D_   512
#define P_   (B_*HW_)          // 4096 positions (b*HW + hw)
#define NCHUNK 32
#define CPC  (C_/NCHUNK)       // 256 c per chunk

#define INV_TAU 1.1111111111111112f       // 1/0.9
#define LOGU   (-9.010913347279288f)      // log(1/8192)

// Scratch (static device allocations; no cudaMalloc allowed)
__device__ float g_onehot[(size_t)P_ * C_];   // 128 MB, [pos][c] row-major
__device__ float g_part1[NCHUNK][P_];
__device__ float g_part2[NCHUNK][P_];
__device__ float g_s1inv[P_];
__device__ float g_logs2[P_];

// ---------------------------------------------------------------------------
// packed f32x2 helpers (sm_100+ PTX)
// ---------------------------------------------------------------------------
__device__ __forceinline__ unsigned long long pack2(float lo, float hi) {
    unsigned long long r;
    asm("mov.b64 %0, {%1, %2};" : "=l"(r) : "f"(lo), "f"(hi));
    return r;
}
__device__ __forceinline__ void unpack2(unsigned long long v, float& lo, float& hi) {
    asm("mov.b64 {%0, %1}, %2;" : "=f"(lo), "=f"(hi) : "l"(v));
}
__device__ __forceinline__ void ffma2(unsigned long long& d,
                                      unsigned long long a,
                                      unsigned long long b) {
    asm("fma.rn.f32x2 %0, %1, %2, %0;" : "+l"(d) : "l"(a), "l"(b));
}

// ---------------------------------------------------------------------------
// Kernel 1: partial sums per (position, c-chunk).
// No max-subtraction needed: (x+g)/tau <= ~27 -> exp fits fp32 comfortably.
// ---------------------------------------------------------------------------
__global__ void k_stats(const float* __restrict__ x, const float* __restrict__ g) {
    int t = threadIdx.x;
    int pos = blockIdx.x * 256 + t;          // 16 blocks * 256 = 4096 positions
    int chunk = blockIdx.y;
    int b = pos >> 10;
    int hw = pos & 1023;
    size_t base = ((size_t)b * C_ + (size_t)chunk * CPC) * HW_ + hw;
    const float* xp = x + base;
    const float* gp = g + base;
    float s1 = 0.f, s2 = 0.f;
#pragma unroll 8
    for (int c = 0; c < CPC; c++) {
        float xv = __ldg(xp + (size_t)c * HW_);
        float gv = __ldg(gp + (size_t)c * HW_);
        s1 += __expf((xv + gv) * INV_TAU);
        s2 += __expf(xv);
    }
    g_part1[chunk][pos] = s1;
    g_part2[chunk][pos] = s2;
}

// ---------------------------------------------------------------------------
// Kernel 1b: deterministic combine of the 32 chunk partials.
// Also zeroes the KL output slot (d_out is poisoned by the harness).
// ---------------------------------------------------------------------------
__global__ void k_combine(float* klp) {
    int pos = blockIdx.x * 256 + threadIdx.x;
    float s1 = 0.f, s2 = 0.f;
#pragma unroll
    for (int k = 0; k < NCHUNK; k++) {
        s1 += g_part1[k][pos];
        s2 += g_part2[k][pos];
    }
    g_s1inv[pos] = 1.0f / s1;
    g_logs2[pos] = logf(s2);
    if (pos == 0 && klp) *klp = 0.0f;
}

// ---------------------------------------------------------------------------
// Kernel 2: transpose + elementwise.
// Reads x,g in [b][c][hw] layout (coalesced along hw), writes logits, log_qy,
// one_hot in [pos][c] layout (coalesced along c) via 32x32 smem tiles.
// Accumulates KL via block reduction + atomicAdd.
// ---------------------------------------------------------------------------
__global__ void k_elem(const float* __restrict__ x, const float* __restrict__ gm,
                       float* __restrict__ logits, float* __restrict__ logqy,
                       float* __restrict__ kl) {
    __shared__ float xs[32][33];
    __shared__ float gs[32][33];
    __shared__ float warpsum[8];

    int tx = threadIdx.x;           // 0..31
    int ty = threadIdx.y;           // 0..7
    int hw0 = blockIdx.x * 32;
    int c0  = blockIdx.y * 32;
    int b   = blockIdx.z;

    // Read phase: rows = c, cols = hw (coalesced along hw)
#pragma unroll
    for (int i = 0; i < 4; i++) {
        int c = c0 + ty + 8 * i;
        size_t idx = ((size_t)b * C_ + c) * HW_ + hw0 + tx;
        xs[ty + 8 * i][tx] = x[idx];
        gs[ty + 8 * i][tx] = gm[idx];
    }
    __syncthreads();

    // Write phase: rows = hw, cols = c (coalesced along c)
    float klacc = 0.f;
#pragma unroll
    for (int i = 0; i < 4; i++) {
        int hwl = ty + 8 * i;
        int hw = hw0 + hwl;
        int pos = (b << 10) + hw;
        float ls2 = g_logs2[pos];
        float s1i = g_s1inv[pos];
        float xv = xs[tx][hwl];
        float gv = gs[tx][hwl];
        size_t o = (size_t)pos * C_ + c0 + tx;
        if (logits) logits[o] = xv;
        float lq = xv - ls2;
        if (logqy) logqy[o] = lq;
        float p = __expf((xv + gv) * INV_TAU) * s1i;
        g_onehot[o] = p;
        klacc += __expf(lq) * (lq - LOGU);
    }

    // KL block reduction: warp = ty, lane = tx
#pragma unroll
    for (int off = 16; off > 0; off >>= 1)
        klacc += __shfl_xor_sync(0xffffffffu, klacc, off);
    if (tx == 0) warpsum[ty] = klacc;
    __syncthreads();
    if (ty == 0 && tx < 8) {
        float v = warpsum[tx];
#pragma unroll
        for (int off = 4; off > 0; off >>= 1)
            v += __shfl_xor_sync(0xffu, v, off);
        if (tx == 0 && kl) atomicAdd(kl, v);
    }
}

// ---------------------------------------------------------------------------
// Kernel 3: GEMM  sampled[b][d][hw] = sum_c one_hot[pos][c] * emb[c][d]
// M=4096 (pos), N=512 (d), K=8192 (c). 128x128x16 tiles, 256 threads,
// 8x8 per thread, inner loop in packed FFMA2 (fma.rn.f32x2).
// ---------------------------------------------------------------------------
#define BM 128
#define BN 128
#define BK 16

__global__ void __launch_bounds__(256) k_gemm(const float* __restrict__ Bmat,
                                              float* __restrict__ out) {
    __shared__ float As[BK][BM];
    __shared__ float Bs[BK][BN];

    int t = threadIdx.x;
    int tx = t & 15;    // -> n
    int ty = t >> 4;    // -> m
    int m0 = blockIdx.x * BM;
    int n0 = blockIdx.y * BN;

    unsigned long long acc[8][4];
#pragma unroll
    for (int i = 0; i < 8; i++)
#pragma unroll
        for (int j = 0; j < 4; j++) acc[i][j] = 0ull;

    const float* Ap = g_onehot + (size_t)m0 * C_;

    for (int k0 = 0; k0 < C_; k0 += BK) {
        // Load A tile 128x16 (transpose into As[k][m])
#pragma unroll
        for (int l = 0; l < 2; l++) {
            int id = t + 256 * l;
            int row = id >> 2;
            int cv = id & 3;
            float4 v = *(const float4*)(Ap + (size_t)row * C_ + k0 + cv * 4);
            As[cv * 4 + 0][row] = v.x;
            As[cv * 4 + 1][row] = v.y;
            As[cv * 4 + 2][row] = v.z;
            As[cv * 4 + 3][row] = v.w;
        }
        // Load B tile 16x128
#pragma unroll
        for (int l = 0; l < 2; l++) {
            int id = t + 256 * l;
            int row = id >> 5;
            int col = id & 31;
            float4 v = *(const float4*)(Bmat + (size_t)(k0 + row) * D_ + n0 + col * 4);
            *(float4*)&Bs[row][col * 4] = v;
        }
        __syncthreads();

#pragma unroll
        for (int kk = 0; kk < BK; kk++) {
            float a[8];
            *(float4*)(a)     = *(const float4*)&As[kk][ty * 8];
            *(float4*)(a + 4) = *(const float4*)&As[kk][ty * 8 + 4];
            unsigned long long b2[4];
#pragma unroll
            for (int j = 0; j < 4; j++)
                b2[j] = *(const unsigned long long*)&Bs[kk][tx * 8 + j * 2];
#pragma unroll
            for (int i = 0; i < 8; i++) {
                unsigned long long aa = pack2(a[i], a[i]);
#pragma unroll
                for (int j = 0; j < 4; j++) ffma2(acc[i][j], aa, b2[j]);
            }
        }
        __syncthreads();
    }

    // Store: out[(b*D + n)*HW + hw], m = b*HW + hw
#pragma unroll
    for (int i = 0; i < 8; i++) {
        int mm = m0 + ty * 8 + i;
        int bb = mm >> 10;
        int hw = mm & 1023;
#pragma unroll
        for (int j = 0; j < 4; j++) {
            float lo, hi;
            unpack2(acc[i][j], lo, hi);
            int n = n0 + tx * 8 + j * 2;
            out[((size_t)(bb * D_ + n)) * HW_ + hw]     = lo;
            out[((size_t)(bb * D_ + n + 1)) * HW_ + hw] = hi;
        }
    }
}

// ---------------------------------------------------------------------------
// Launch. Output layout (concatenated, reference return order):
//   sampled [B*D*HW] | kl [1] | logits [B*HW*C] | log_qy [B*HW*C]
// Defensive on out_size in case only a prefix is requested.
// ---------------------------------------------------------------------------
extern "C" void kernel_launch(void* const* d_in, const int* in_sizes, int n_in,
                              void* d_out, int out_size) {
    const float* x   = (const float*)d_in[0];
    const float* gm  = (const float*)d_in[1];
    const float* emb = (const float*)d_in[2];
    float* out = (float*)d_out;

    const long long N_SAMP = (long long)B_ * D_ * HW_;    // 2097152
    const long long N_LG   = (long long)B_ * HW_ * C_;    // 33554432

    float* logits = nullptr;
    float* logqy  = nullptr;
    float* kl     = nullptr;
    if ((long long)out_size >= N_SAMP + 1 + 2 * N_LG) {
        kl     = out + N_SAMP;
        logits = out + N_SAMP + 1;
        logqy  = logits + N_LG;
    } else if ((long long)out_size >= N_SAMP + 1 + N_LG) {
        kl     = out + N_SAMP;
        logits = out + N_SAMP + 1;
    } else if ((long long)out_size >= N_SAMP + 1) {
        kl = out + N_SAMP;
    }

    k_stats<<<dim3(16, NCHUNK), 256>>>(x, gm);
    k_combine<<<16, 256>>>(kl);
    k_elem<<<dim3(HW_ / 32, C_ / 32, B_), dim3(32, 8)>>>(x, gm, logits, logqy, kl);
    k_gemm<<<dim3(P_ / BM, D_ / BN), 256>>>(emb, out);
}

// round 4
// speedup vs baseline: 2.3488x; 2.3488x over previous
#include <cuda_runtime.h>
#include <cuda_bf16.h>
#include <cstdint>

// Problem constants
#define B_   4
#define C_   8192
#define HW_  1024
#define D_   512
#define P_   (B_*HW_)          // 4096 positions (b*HW + hw)
#define NCHUNK 32
#define CPC  (C_/NCHUNK)       // 256 c per chunk

#define INV_TAU 1.1111111111111112f       // 1/0.9
#define LOGU   (-9.010913347279288f)      // log(1/8192)

// GEMM tiling (mma.sync path — baseline PTX only, no tcgen05)
#define BM 128
#define BN 128
#define BK 32
#define NKC (C_/BK)            // 256 k-chunks
#define ROWB 80                // smem bytes per 32-bf16 row (padded, conflict-free)
#define MATB (128*ROWB)        // 10240 bytes per matrix tile
#define STG  (4*MATB)          // Ah, Al, Bh, Bl per stage = 40960
#define SMEM_GEMM (2*STG)      // 81920

// Scratch (static device arrays; no cudaMalloc allowed)
__device__ __nv_bfloat16 g_ah[(size_t)P_ * C_];   // one_hot hi  (64 MB)
__device__ __nv_bfloat16 g_al[(size_t)P_ * C_];   // one_hot lo  (64 MB)
__device__ __nv_bfloat16 g_bh[(size_t)D_ * C_];   // emb^T hi    (8 MB)
__device__ __nv_bfloat16 g_bl[(size_t)D_ * C_];   // emb^T lo    (8 MB)
__device__ float g_part1[NCHUNK][P_];
__device__ float g_part2[NCHUNK][P_];
__device__ float g_s1inv[P_];
__device__ float g_logs2[P_];

// ---------------------------------------------------------------------------
// Baseline-PTX helpers
// ---------------------------------------------------------------------------
__device__ __forceinline__ uint32_t smem_u32(const void* p) {
    uint32_t a;
    asm("{ .reg .u64 t; cvta.to.shared.u64 t, %1; cvt.u32.u64 %0, t; }" : "=r"(a) : "l"(p));
    return a;
}
__device__ __forceinline__ void cp16(uint32_t s, const void* g) {
    asm volatile("cp.async.cg.shared.global [%0], [%1], 16;" :: "r"(s), "l"(g));
}
__device__ __forceinline__ void cp_commit() {
    asm volatile("cp.async.commit_group;");
}
template<int N> __device__ __forceinline__ void cp_wait() {
    asm volatile("cp.async.wait_group %0;" :: "n"(N));
}
__device__ __forceinline__ void ldsm4(uint32_t* r, uint32_t a) {
    asm volatile("ldmatrix.sync.aligned.m8n8.x4.shared.b16 {%0,%1,%2,%3}, [%4];"
                 : "=r"(r[0]), "=r"(r[1]), "=r"(r[2]), "=r"(r[3]) : "r"(a));
}
__device__ __forceinline__ void mma16816(float* d, const uint32_t* a, const uint32_t* b) {
    asm volatile("mma.sync.aligned.m16n8k16.row.col.f32.bf16.bf16.f32 "
                 "{%0,%1,%2,%3}, {%4,%5,%6,%7}, {%8,%9}, {%0,%1,%2,%3};"
                 : "+f"(d[0]), "+f"(d[1]), "+f"(d[2]), "+f"(d[3])
                 : "r"(a[0]), "r"(a[1]), "r"(a[2]), "r"(a[3]), "r"(b[0]), "r"(b[1]));
}

// ---------------------------------------------------------------------------
// Kernel 0: emb [c][d] fp32 -> g_bh/g_bl [d][c] bf16 hi/lo (transpose + split)
// ---------------------------------------------------------------------------
__global__ void k_conv(const float* __restrict__ emb) {
    __shared__ float ts[32][33];
    int tx = threadIdx.x, ty = threadIdx.y;
    int c0 = blockIdx.x * 32, d0 = blockIdx.y * 32;
#pragma unroll
    for (int i = 0; i < 4; i++)
        ts[ty + 8 * i][tx] = emb[(size_t)(c0 + ty + 8 * i) * D_ + d0 + tx];
    __syncthreads();
#pragma unroll
    for (int i = 0; i < 4; i++) {
        int d = d0 + ty + 8 * i;
        int c = c0 + tx;
        float v = ts[tx][ty + 8 * i];
        __nv_bfloat16 h = __float2bfloat16(v);
        __nv_bfloat16 l = __float2bfloat16(v - __bfloat162float(h));
        g_bh[(size_t)d * C_ + c] = h;
        g_bl[(size_t)d * C_ + c] = l;
    }
}

// ---------------------------------------------------------------------------
// Kernel 1: partial sums per (position, c-chunk). No max-subtraction needed:
// (x+g)/tau <= ~27 -> exp fits fp32.
// ---------------------------------------------------------------------------
__global__ void k_stats(const float* __restrict__ x, const float* __restrict__ g) {
    int t = threadIdx.x;
    int pos = blockIdx.x * 256 + t;
    int chunk = blockIdx.y;
    int b = pos >> 10;
    int hw = pos & 1023;
    size_t base = ((size_t)b * C_ + (size_t)chunk * CPC) * HW_ + hw;
    const float* xp = x + base;
    const float* gp = g + base;
    float s1 = 0.f, s2 = 0.f;
#pragma unroll 8
    for (int c = 0; c < CPC; c++) {
        float xv = __ldg(xp + (size_t)c * HW_);
        float gv = __ldg(gp + (size_t)c * HW_);
        s1 += __expf((xv + gv) * INV_TAU);
        s2 += __expf(xv);
    }
    g_part1[chunk][pos] = s1;
    g_part2[chunk][pos] = s2;
}

__global__ void k_combine(float* klp) {
    int pos = blockIdx.x * 256 + threadIdx.x;
    float s1 = 0.f, s2 = 0.f;
#pragma unroll
    for (int k = 0; k < NCHUNK; k++) {
        s1 += g_part1[k][pos];
        s2 += g_part2[k][pos];
    }
    g_s1inv[pos] = 1.0f / s1;
    g_logs2[pos] = logf(s2);
    if (pos == 0 && klp) *klp = 0.0f;
}

// ---------------------------------------------------------------------------
// Kernel 2: transpose + elementwise. Writes logits, log_qy, and one_hot as
// bf16 hi/lo pairs in [pos][c] layout. Accumulates KL.
// ---------------------------------------------------------------------------
__global__ void k_elem(const float* __restrict__ x, const float* __restrict__ gm,
                       float* __restrict__ logits, float* __restrict__ logqy,
                       float* __restrict__ kl) {
    __shared__ float xs[32][33];
    __shared__ float gs[32][33];
    __shared__ float warpsum[8];

    int tx = threadIdx.x, ty = threadIdx.y;
    int hw0 = blockIdx.x * 32;
    int c0  = blockIdx.y * 32;
    int b   = blockIdx.z;

#pragma unroll
    for (int i = 0; i < 4; i++) {
        int c = c0 + ty + 8 * i;
        size_t idx = ((size_t)b * C_ + c) * HW_ + hw0 + tx;
        xs[ty + 8 * i][tx] = x[idx];
        gs[ty + 8 * i][tx] = gm[idx];
    }
    __syncthreads();

    float klacc = 0.f;
#pragma unroll
    for (int i = 0; i < 4; i++) {
        int hwl = ty + 8 * i;
        int hw = hw0 + hwl;
        int pos = (b << 10) + hw;
        float ls2 = g_logs2[pos];
        float s1i = g_s1inv[pos];
        float xv = xs[tx][hwl];
        float gv = gs[tx][hwl];
        size_t o = (size_t)pos * C_ + c0 + tx;
        if (logits) logits[o] = xv;
        float lq = xv - ls2;
        if (logqy) logqy[o] = lq;
        float p = __expf((xv + gv) * INV_TAU) * s1i;
        __nv_bfloat16 h = __float2bfloat16(p);
        g_ah[o] = h;
        g_al[o] = __float2bfloat16(p - __bfloat162float(h));
        klacc += __expf(lq) * (lq - LOGU);
    }

#pragma unroll
    for (int off = 16; off > 0; off >>= 1)
        klacc += __shfl_xor_sync(0xffffffffu, klacc, off);
    if (tx == 0) warpsum[ty] = klacc;
    __syncthreads();
    if (ty == 0 && tx < 8) {
        float v = warpsum[tx];
#pragma unroll
        for (int off = 4; off > 0; off >>= 1)
            v += __shfl_xor_sync(0xffu, v, off);
        if (tx == 0 && kl) atomicAdd(kl, v);
    }
}

// ---------------------------------------------------------------------------
// Kernel 3: mma.sync split-bf16 GEMM.
// D[m,n] = sum_c one_hot[m,c]*embT[n,c]  via ah*bh + ah*bl + al*bh, fp32 acc.
// 128x128 tiles, BK=32, cp.async double buffering, 8 warps (2x4), 64x32/warp.
// smem rows padded to 80B: 8 consecutive rows at one 16B column hit 8
// distinct 16B groups mod 128 -> conflict-free ldmatrix without swizzle.
// ---------------------------------------------------------------------------
__device__ __forceinline__ void issue_stage(uint32_t sb, int k0,
                                            const uint32_t* goff,
                                            const uint32_t* soff) {
#pragma unroll
    for (int l = 0; l < 8; l++) {
        const __nv_bfloat16* base = (l < 2) ? g_ah : (l < 4) ? g_al
                                  : (l < 6) ? g_bh : g_bl;
        cp16(sb + soff[l], base + goff[l] + k0);
    }
}

__global__ void __launch_bounds__(256) k_gemm_mma(float* __restrict__ out) {
    extern __shared__ __align__(16) char sm[];
    uint32_t sbase = smem_u32(sm);
    int t = threadIdx.x, lid = t & 31, wid = t >> 5;
    int m0 = blockIdx.x * BM, n0 = blockIdx.y * BN;
    int wm = (wid >> 2) * 64;    // warp m offset: 0 or 64
    int wn = (wid & 3) * 32;     // warp n offset: 0..96

    // per-thread cp.async slots: 8 x 16B per stage
    uint32_t goff[8], soff[8];
#pragma unroll
    for (int l = 0; l < 8; l++) {
        int idx = (t + 256 * l) & 511;
        int row = idx >> 2, cu = idx & 3;
        int r0 = ((l < 4) ? m0 : n0) + row;
        goff[l] = (uint32_t)r0 * C_ + cu * 8;
        soff[l] = (uint32_t)(l >> 1) * MATB + row * ROWB + cu * 16;
    }

    // ldmatrix lane offsets
    uint32_t aoff = (uint32_t)(wm + (lid & 15)) * ROWB + ((lid >> 4) << 4);
    uint32_t boff = (uint32_t)(wn + ((lid >> 4) << 3) + (lid & 7)) * ROWB +
                    (((lid >> 3) & 1) << 4);

    float acc[4][4][4];
#pragma unroll
    for (int i = 0; i < 4; i++)
#pragma unroll
        for (int j = 0; j < 4; j++)
#pragma unroll
            for (int q = 0; q < 4; q++) acc[i][j][q] = 0.f;

    issue_stage(sbase, 0, goff, soff);            cp_commit();
    issue_stage(sbase + STG, BK, goff, soff);     cp_commit();

    for (int kc = 0; kc < NKC; kc++) {
        cp_wait<1>();
        __syncthreads();
        uint32_t sb = sbase + (uint32_t)(kc & 1) * STG;
#pragma unroll
        for (int kh = 0; kh < 2; kh++) {
            uint32_t ah[4][4], al[4][4], bh[8], bl[8];
#pragma unroll
            for (int mt = 0; mt < 4; mt++) {
                ldsm4(ah[mt], sb + 0 * MATB + aoff + mt * (16 * ROWB) + kh * 32);
                ldsm4(al[mt], sb + 1 * MATB + aoff + mt * (16 * ROWB) + kh * 32);
            }
#pragma unroll
            for (int j = 0; j < 2; j++) {
                ldsm4(&bh[j * 4], sb + 2 * MATB + boff + j * (16 * ROWB) + kh * 32);
                ldsm4(&bl[j * 4], sb + 3 * MATB + boff + j * (16 * ROWB) + kh * 32);
            }
#pragma unroll
            for (int mt = 0; mt < 4; mt++)
#pragma unroll
                for (int nt = 0; nt < 4; nt++) {
                    mma16816(acc[mt][nt], ah[mt], &bh[nt * 2]);
                    mma16816(acc[mt][nt], ah[mt], &bl[nt * 2]);
                    mma16816(acc[mt][nt], al[mt], &bh[nt * 2]);
                }
        }
        __syncthreads();
        if (kc + 2 < NKC) issue_stage(sbase + (uint32_t)(kc & 1) * STG,
                                      (kc + 2) * BK, goff, soff);
        cp_commit();
    }

    // Epilogue: stage [n][m] in smem, then coalesced float4 stores along hw.
    __syncthreads();
    float* so = (float*)sm;
    int g = lid >> 2, tt = lid & 3;
#pragma unroll
    for (int mt = 0; mt < 4; mt++)
#pragma unroll
        for (int nt = 0; nt < 4; nt++) {
            int nl = wn + nt * 8 + 2 * tt;
            int ml = wm + mt * 16 + g;
            so[nl * 128 + ml]               = acc[mt][nt][0];
            so[(nl + 1) * 128 + ml]         = acc[mt][nt][1];
            so[nl * 128 + ml + 8]           = acc[mt][nt][2];
            so[(nl + 1) * 128 + ml + 8]     = acc[mt][nt][3];
        }
    __syncthreads();
    int bb = m0 >> 10, hw0 = m0 & 1023;
#pragma unroll
    for (int it = 0; it < 16; it++) {
        int idx = t + 256 * it;
        int n = idx >> 5, mq = (idx & 31) * 4;
        float4 v = *(float4*)&so[n * 128 + mq];
        *(float4*)&out[((size_t)bb * D_ + n0 + n) * HW_ + hw0 + mq] = v;
    }
}

// ---------------------------------------------------------------------------
// Launch. Output layout: sampled [B*D*HW] | kl [1] | logits [B*HW*C] | log_qy
// ---------------------------------------------------------------------------
extern "C" void kernel_launch(void* const* d_in, const int* in_sizes, int n_in,
                              void* d_out, int out_size) {
    const float* x   = (const float*)d_in[0];
    const float* gm  = (const float*)d_in[1];
    const float* emb = (const float*)d_in[2];
    float* out = (float*)d_out;

    const long long N_SAMP = (long long)B_ * D_ * HW_;
    const long long N_LG   = (long long)B_ * HW_ * C_;

    float* logits = nullptr;
    float* logqy  = nullptr;
    float* kl     = nullptr;
    if ((long long)out_size >= N_SAMP + 1 + 2 * N_LG) {
        kl     = out + N_SAMP;
        logits = out + N_SAMP + 1;
        logqy  = logits + N_LG;
    } else if ((long long)out_size >= N_SAMP + 1 + N_LG) {
        kl     = out + N_SAMP;
        logits = out + N_SAMP + 1;
    } else if ((long long)out_size >= N_SAMP + 1) {
        kl = out + N_SAMP;
    }

    static bool attr_done = false;
    if (!attr_done) {
        cudaFuncSetAttribute(k_gemm_mma, cudaFuncAttributeMaxDynamicSharedMemorySize,
                             SMEM_GEMM);
        attr_done = true;
    }

    k_conv<<<dim3(C_ / 32, D_ / 32), dim3(32, 8)>>>(emb);
    k_stats<<<dim3(16, NCHUNK), 256>>>(x, gm);
    k_combine<<<16, 256>>>(kl);
    k_elem<<<dim3(HW_ / 32, C_ / 32, B_), dim3(32, 8)>>>(x, gm, logits, logqy, kl);
    k_gemm_mma<<<dim3(P_ / BM, D_ / BN), 256, SMEM_GEMM>>>(out);
}

// round 6
// speedup vs baseline: 2.4275x; 1.0335x over previous
#include <cuda_runtime.h>
#include <cuda_bf16.h>
#include <cstdint>

// Problem constants
#define B_   4
#define C_   8192
#define HW_  1024
#define D_   512
#define P_   (B_*HW_)          // 4096 positions (b*HW + hw)
#define NCHUNK 32
#define CPC  (C_/NCHUNK)       // 256 c per chunk

#define INV_TAU 1.1111111111111112f       // 1/0.9
#define LOGU   (-9.010913347279288f)      // log(1/8192)

// GEMM tiling (mma.sync path — baseline PTX only, no tcgen05)
#define BM 128
#define BN 128
#define BK 32
#define NKC (C_/BK)            // 256 k-chunks
#define ROWB 80                // smem bytes per 32-bf16 row (padded, conflict-free)
#define MATB (128*ROWB)        // 10240 bytes per matrix tile
#define STG  (4*MATB)          // Ah, Al, Bh, Bl per stage = 40960
#define NSTAGE 3
#define SMEM_GEMM (NSTAGE*STG) // 122880

// Scratch (static device arrays; no cudaMalloc allowed)
__device__ __nv_bfloat16 g_ah[(size_t)P_ * C_];   // one_hot hi  (64 MB)
__device__ __nv_bfloat16 g_al[(size_t)P_ * C_];   // one_hot lo  (64 MB)
__device__ __nv_bfloat16 g_bh[(size_t)D_ * C_];   // emb^T hi    (8 MB)
__device__ __nv_bfloat16 g_bl[(size_t)D_ * C_];   // emb^T lo    (8 MB)
__device__ float g_part1[NCHUNK][P_];
__device__ float g_part2[NCHUNK][P_];
__device__ float g_s1inv[P_];
__device__ float g_logs2[P_];

// ---------------------------------------------------------------------------
// Baseline-PTX helpers
// ---------------------------------------------------------------------------
__device__ __forceinline__ uint32_t smem_u32(const void* p) {
    uint32_t a;
    asm("{ .reg .u64 t; cvta.to.shared.u64 t, %1; cvt.u32.u64 %0, t; }" : "=r"(a) : "l"(p));
    return a;
}
__device__ __forceinline__ void cp16(uint32_t s, const void* g) {
    asm volatile("cp.async.cg.shared.global [%0], [%1], 16;" :: "r"(s), "l"(g));
}
__device__ __forceinline__ void cp_commit() {
    asm volatile("cp.async.commit_group;");
}
template<int N> __device__ __forceinline__ void cp_wait() {
    asm volatile("cp.async.wait_group %0;" :: "n"(N));
}
__device__ __forceinline__ void ldsm4(uint32_t* r, uint32_t a) {
    asm volatile("ldmatrix.sync.aligned.m8n8.x4.shared.b16 {%0,%1,%2,%3}, [%4];"
                 : "=r"(r[0]), "=r"(r[1]), "=r"(r[2]), "=r"(r[3]) : "r"(a));
}
__device__ __forceinline__ void mma16816(float* d, const uint32_t* a, const uint32_t* b) {
    asm volatile("mma.sync.aligned.m16n8k16.row.col.f32.bf16.bf16.f32 "
                 "{%0,%1,%2,%3}, {%4,%5,%6,%7}, {%8,%9}, {%0,%1,%2,%3};"
                 : "+f"(d[0]), "+f"(d[1]), "+f"(d[2]), "+f"(d[3])
                 : "r"(a[0]), "r"(a[1]), "r"(a[2]), "r"(a[3]), "r"(b[0]), "r"(b[1]));
}

// ---------------------------------------------------------------------------
// Kernel 0: emb [c][d] fp32 -> g_bh/g_bl [d][c] bf16 hi/lo (transpose + split)
// ---------------------------------------------------------------------------
__global__ void k_conv(const float* __restrict__ emb) {
    __shared__ float ts[32][33];
    int tx = threadIdx.x, ty = threadIdx.y;
    int c0 = blockIdx.x * 32, d0 = blockIdx.y * 32;
#pragma unroll
    for (int i = 0; i < 4; i++)
        ts[ty + 8 * i][tx] = emb[(size_t)(c0 + ty + 8 * i) * D_ + d0 + tx];
    __syncthreads();
#pragma unroll
    for (int i = 0; i < 4; i++) {
        int d = d0 + ty + 8 * i;
        int c = c0 + tx;
        float v = ts[tx][ty + 8 * i];
        __nv_bfloat16 h = __float2bfloat16(v);
        __nv_bfloat16 l = __float2bfloat16(v - __bfloat162float(h));
        g_bh[(size_t)d * C_ + c] = h;
        g_bl[(size_t)d * C_ + c] = l;
    }
}

// ---------------------------------------------------------------------------
// Kernel 1: partial sums per (position, c-chunk). No max-subtraction needed:
// (x+g)/tau <= ~27 -> exp fits fp32.
// ---------------------------------------------------------------------------
__global__ void k_stats(const float* __restrict__ x, const float* __restrict__ g) {
    int t = threadIdx.x;
    int pos = blockIdx.x * 256 + t;
    int chunk = blockIdx.y;
    int b = pos >> 10;
    int hw = pos & 1023;
    size_t base = ((size_t)b * C_ + (size_t)chunk * CPC) * HW_ + hw;
    const float* xp = x + base;
    const float* gp = g + base;
    float s1 = 0.f, s2 = 0.f;
#pragma unroll 8
    for (int c = 0; c < CPC; c++) {
        float xv = __ldg(xp + (size_t)c * HW_);
        float gv = __ldg(gp + (size_t)c * HW_);
        s1 += __expf((xv + gv) * INV_TAU);
        s2 += __expf(xv);
    }
    g_part1[chunk][pos] = s1;
    g_part2[chunk][pos] = s2;
}

__global__ void k_combine(float* klp) {
    int pos = blockIdx.x * 256 + threadIdx.x;
    float s1 = 0.f, s2 = 0.f;
#pragma unroll
    for (int k = 0; k < NCHUNK; k++) {
        s1 += g_part1[k][pos];
        s2 += g_part2[k][pos];
    }
    g_s1inv[pos] = 1.0f / s1;
    g_logs2[pos] = logf(s2);
    if (pos == 0 && klp) *klp = 0.0f;
}

// ---------------------------------------------------------------------------
// Kernel 2: transpose + elementwise. 64c x 32hw tile; each thread owns a
// c-pair. g_ah/g_al get vector bfloat162 stores (aligned device arrays);
// logits/log_qy use scalar stores because their base pointer is odd-offset
// within d_out (only 4B-aligned).
// ---------------------------------------------------------------------------
__global__ void k_elem(const float* __restrict__ x, const float* __restrict__ gm,
                       float* __restrict__ logits, float* __restrict__ logqy,
                       float* __restrict__ kl) {
    __shared__ __align__(16) float xs[32][66];
    __shared__ __align__(16) float gs[32][66];
    __shared__ float warpsum[8];

    int tx = threadIdx.x, ty = threadIdx.y;
    int t = ty * 32 + tx;
    int hw0 = blockIdx.x * 32;
    int c0  = blockIdx.y * 64;
    int b   = blockIdx.z;

    // Fill: 64 c-rows x 32 hw, coalesced along hw, stored transposed.
#pragma unroll
    for (int i = 0; i < 8; i++) {
        int idx = t + 256 * i;
        int c = idx >> 5;
        int hw = idx & 31;
        size_t src = ((size_t)b * C_ + c0 + c) * HW_ + hw0 + hw;
        xs[hw][c] = x[src];
        gs[hw][c] = gm[src];
    }
    __syncthreads();

    float klacc = 0.f;
#pragma unroll
    for (int i = 0; i < 4; i++) {
        int hwl = ty + 8 * i;
        int pos = (b << 10) + hw0 + hwl;
        float ls2 = g_logs2[pos];
        float s1i = g_s1inv[pos];
        float2 xv = *(float2*)&xs[hwl][2 * tx];
        float2 gv = *(float2*)&gs[hwl][2 * tx];
        size_t o = (size_t)pos * C_ + c0 + 2 * tx;

        if (logits) { logits[o] = xv.x; logits[o + 1] = xv.y; }
        float lq0 = xv.x - ls2, lq1 = xv.y - ls2;
        if (logqy) { logqy[o] = lq0; logqy[o + 1] = lq1; }

        float p0 = __expf((xv.x + gv.x) * INV_TAU) * s1i;
        float p1 = __expf((xv.y + gv.y) * INV_TAU) * s1i;
        __nv_bfloat16 h0 = __float2bfloat16(p0);
        __nv_bfloat16 h1 = __float2bfloat16(p1);
        __nv_bfloat162 hh; hh.x = h0; hh.y = h1;
        *(__nv_bfloat162*)(g_ah + o) = hh;
        __nv_bfloat162 ll;
        ll.x = __float2bfloat16(p0 - __bfloat162float(h0));
        ll.y = __float2bfloat16(p1 - __bfloat162float(h1));
        *(__nv_bfloat162*)(g_al + o) = ll;

        klacc += __expf(lq0) * (lq0 - LOGU) + __expf(lq1) * (lq1 - LOGU);
    }

#pragma unroll
    for (int off = 16; off > 0; off >>= 1)
        klacc += __shfl_xor_sync(0xffffffffu, klacc, off);
    if (tx == 0) warpsum[ty] = klacc;
    __syncthreads();
    if (ty == 0 && tx < 8) {
        float v = warpsum[tx];
#pragma unroll
        for (int off = 4; off > 0; off >>= 1)
            v += __shfl_xor_sync(0xffu, v, off);
        if (tx == 0 && kl) atomicAdd(kl, v);
    }
}

// ---------------------------------------------------------------------------
// Kernel 3: mma.sync split-bf16 GEMM, 3-stage cp.async pipeline,
// one __syncthreads per k-chunk.
// ---------------------------------------------------------------------------
__device__ __forceinline__ void issue_stage(uint32_t sb, int k0,
                                            const uint32_t* goff,
                                            const uint32_t* soff) {
#pragma unroll
    for (int l = 0; l < 8; l++) {
        const __nv_bfloat16* base = (l < 2) ? g_ah : (l < 4) ? g_al
                                  : (l < 6) ? g_bh : g_bl;
        cp16(sb + soff[l], base + goff[l] + k0);
    }
}

__global__ void __launch_bounds__(256) k_gemm_mma(float* __restrict__ out) {
    extern __shared__ __align__(16) char sm[];
    uint32_t sbase = smem_u32(sm);
    int t = threadIdx.x, lid = t & 31, wid = t >> 5;
    int m0 = blockIdx.x * BM, n0 = blockIdx.y * BN;
    int wm = (wid >> 2) * 64;    // warp m offset: 0 or 64
    int wn = (wid & 3) * 32;     // warp n offset: 0..96

    // per-thread cp.async slots: 8 x 16B per stage
    uint32_t goff[8], soff[8];
#pragma unroll
    for (int l = 0; l < 8; l++) {
        int idx = (t + 256 * l) & 511;
        int row = idx >> 2, cu = idx & 3;
        int r0 = ((l < 4) ? m0 : n0) + row;
        goff[l] = (uint32_t)r0 * C_ + cu * 8;
        soff[l] = (uint32_t)(l >> 1) * MATB + row * ROWB + cu * 16;
    }

    // ldmatrix lane offsets
    uint32_t aoff = (uint32_t)(wm + (lid & 15)) * ROWB + ((lid >> 4) << 4);
    uint32_t boff = (uint32_t)(wn + ((lid >> 4) << 3) + (lid & 7)) * ROWB +
                    (((lid >> 3) & 1) << 4);

    float acc[4][4][4];
#pragma unroll
    for (int i = 0; i < 4; i++)
#pragma unroll
        for (int j = 0; j < 4; j++)
#pragma unroll
            for (int q = 0; q < 4; q++) acc[i][j][q] = 0.f;

    issue_stage(sbase, 0, goff, soff);            cp_commit();
    issue_stage(sbase + STG, BK, goff, soff);     cp_commit();

    int stage_rd = 0, stage_wr = 2;
    for (int kc = 0; kc < NKC; kc++) {
        cp_wait<1>();
        __syncthreads();
        // issue the chunk 2 ahead into the buffer last read at kc-1
        if (kc + 2 < NKC)
            issue_stage(sbase + (uint32_t)stage_wr * STG, (kc + 2) * BK, goff, soff);
        cp_commit();
        uint32_t sb = sbase + (uint32_t)stage_rd * STG;
#pragma unroll
        for (int kh = 0; kh < 2; kh++) {
            uint32_t ah[4][4], al[4][4], bh[8], bl[8];
#pragma unroll
            for (int mt = 0; mt < 4; mt++) {
                ldsm4(ah[mt], sb + 0 * MATB + aoff + mt * (16 * ROWB) + kh * 32);
                ldsm4(al[mt], sb + 1 * MATB + aoff + mt * (16 * ROWB) + kh * 32);
            }
#pragma unroll
            for (int j = 0; j < 2; j++) {
                ldsm4(&bh[j * 4], sb + 2 * MATB + boff + j * (16 * ROWB) + kh * 32);
                ldsm4(&bl[j * 4], sb + 3 * MATB + boff + j * (16 * ROWB) + kh * 32);
            }
#pragma unroll
            for (int mt = 0; mt < 4; mt++)
#pragma unroll
                for (int nt = 0; nt < 4; nt++) {
                    mma16816(acc[mt][nt], ah[mt], &bh[nt * 2]);
                    mma16816(acc[mt][nt], ah[mt], &bl[nt * 2]);
                    mma16816(acc[mt][nt], al[mt], &bh[nt * 2]);
                }
        }
        stage_rd = (stage_rd == 2) ? 0 : stage_rd + 1;
        stage_wr = (stage_wr == 2) ? 0 : stage_wr + 1;
    }

    // Epilogue: stage [n][m] in smem, then coalesced float4 stores along hw.
    __syncthreads();
    float* so = (float*)sm;
    int g = lid >> 2, tt = lid & 3;
#pragma unroll
    for (int mt = 0; mt < 4; mt++)
#pragma unroll
        for (int nt = 0; nt < 4; nt++) {
            int nl = wn + nt * 8 + 2 * tt;
            int ml = wm + mt * 16 + g;
            so[nl * 128 + ml]               = acc[mt][nt][0];
            so[(nl + 1) * 128 + ml]         = acc[mt][nt][1];
            so[nl * 128 + ml + 8]           = acc[mt][nt][2];
            so[(nl + 1) * 128 + ml + 8]     = acc[mt][nt][3];
        }
    __syncthreads();
    int bb = m0 >> 10, hw0 = m0 & 1023;
#pragma unroll
    for (int it = 0; it < 16; it++) {
        int idx = t + 256 * it;
        int n = idx >> 5, mq = (idx & 31) * 4;
        float4 v = *(float4*)&so[n * 128 + mq];
        *(float4*)&out[((size_t)bb * D_ + n0 + n) * HW_ + hw0 + mq] = v;
    }
}

// ---------------------------------------------------------------------------
// Launch. Output layout: sampled [B*D*HW] | kl [1] | logits [B*HW*C] | log_qy
// ---------------------------------------------------------------------------
extern "C" void kernel_launch(void* const* d_in, const int* in_sizes, int n_in,
                              void* d_out, int out_size) {
    const float* x   = (const float*)d_in[0];
    const float* gm  = (const float*)d_in[1];
    const float* emb = (const float*)d_in[2];
    float* out = (float*)d_out;

    const long long N_SAMP = (long long)B_ * D_ * HW_;
    const long long N_LG   = (long long)B_ * HW_ * C_;

    float* logits = nullptr;
    float* logqy  = nullptr;
    float* kl     = nullptr;
    if ((long long)out_size >= N_SAMP + 1 + 2 * N_LG) {
        kl     = out + N_SAMP;
        logits = out + N_SAMP + 1;
        logqy  = logits + N_LG;
    } else if ((long long)out_size >= N_SAMP + 1 + N_LG) {
        kl     = out + N_SAMP;
        logits = out + N_SAMP + 1;
    } else if ((long long)out_size >= N_SAMP + 1) {
        kl = out + N_SAMP;
    }

    static bool attr_done = false;
    if (!attr_done) {
        cudaFuncSetAttribute(k_gemm_mma, cudaFuncAttributeMaxDynamicSharedMemorySize,
                             SMEM_GEMM);
        attr_done = true;
    }

    k_conv<<<dim3(C_ / 32, D_ / 32), dim3(32, 8)>>>(emb);
    k_stats<<<dim3(16, NCHUNK), 256>>>(x, gm);
    k_combine<<<16, 256>>>(kl);
    k_elem<<<dim3(HW_ / 32, C_ / 64, B_), dim3(32, 8)>>>(x, gm, logits, logqy, kl);
    k_gemm_mma<<<dim3(P_ / BM, D_ / BN), 256, SMEM_GEMM>>>(out);
}